// round 15
// baseline (speedup 1.0000x reference)
#include <cuda_runtime.h>

// ---------------- problem constants ----------------
#define NL   16
#define DM   1024
#define NH   16
#define NKV  8
#define DH   128
#define SEQ  4096
#define FF   4096
#define VOC  32000

#define NPQ  64    // qkv row partials (16 rows each)
#define NPG  64    // gate/up row partials (16 rows each)
#define NPL  16    // lm row partials (64 rows each)
#define NCH  32    // attention chunks of 128

#define NTOT 67108864L              // cache elements per tensor
#define TQ   16777215L              // dest quads ((N-3)>>2)

// ---------------- scratch ----------------
__device__ __align__(16) float g_x[DM];
__device__ __align__(16) float g_qkv_part[NPQ][4096];
__device__ float g_attn_m[NKV][NCH][2];
__device__ float g_attn_l[NKV][NCH][2];
__device__ __align__(16) float g_attn_o[NKV][NCH][2][DH];
__device__ __align__(16) float g_gu_part[NPG][2*FF];
__device__ __align__(16) float g_lm_part[NPL][VOC];
__device__ float g_amax_val[128];
__device__ int   g_amax_idx[128];

__device__ __forceinline__ void fma4(float4& acc, float a, const float4& w) {
    acc.x += a * w.x; acc.y += a * w.y; acc.z += a * w.z; acc.w += a * w.w;
}

// Block rmsnorm rstd from src[DM] (256 threads). Uses sm[0..8].
__device__ __forceinline__ float block_rstd_src(const float* __restrict__ src,
                                                int tid, float* sm) {
    float4 xv = ((const float4*)src)[tid];
    float ss = xv.x*xv.x + xv.y*xv.y + xv.z*xv.z + xv.w*xv.w;
    #pragma unroll
    for (int o = 16; o > 0; o >>= 1) ss += __shfl_down_sync(0xffffffffu, ss, o);
    if ((tid & 31) == 0) sm[tid >> 5] = ss;
    __syncthreads();
    if (tid == 0) {
        float t = 0.f;
        #pragma unroll
        for (int i = 0; i < 8; ++i) t += sm[i];
        sm[8] = rsqrtf(t * (1.0f / DM) + 1e-6f);
    }
    __syncthreads();
    return sm[8];
}

// ---------------- KV cache copy (parallel stream; skips ALL rows at pos) ---
__global__ void k_copy2(const float* __restrict__ a, const float* __restrict__ b,
                        float* __restrict__ oa, float* __restrict__ ob,
                        const int* __restrict__ stepp, const int* __restrict__ plen)
{
    int pos = stepp[0] + plen[0];
    const float4* a4 = (const float4*)a;
    const float4* b4 = (const float4*)b;
    float4* oa4 = (float4*)(oa + 3);
    float4* ob4 = (float4*)(ob + 3);
    long t = (long)blockIdx.x * blockDim.x + threadIdx.x;
    long st = (long)gridDim.x * blockDim.x;
    for (; t < TQ; t += st) {
        long e0 = 4*t + 3;
        int s0 = (int)(e0 >> 7) & (SEQ - 1);
        int s1 = (int)((e0 + 3) >> 7) & (SEQ - 1);
        float4 A = a4[t], B = a4[t + 1];
        float4 r; r.x = A.w; r.y = B.x; r.z = B.y; r.w = B.z;
        if (s0 != pos && s1 != pos) {
            __stcs(oa4 + t, r);
            A = b4[t]; B = b4[t + 1];
            r.x = A.w; r.y = B.x; r.z = B.y; r.w = B.z;
            __stcs(ob4 + t, r);
        } else {
            float ra[4] = {A.w, B.x, B.y, B.z};
            A = b4[t]; B = b4[t + 1];
            float rb[4] = {A.w, B.x, B.y, B.z};
            #pragma unroll
            for (int k = 0; k < 4; ++k) {
                long e = e0 + k;
                if ((((int)(e >> 7)) & (SEQ - 1)) != pos) {
                    oa[e] = ra[k]; ob[e] = rb[k];
                }
            }
        }
    }
    if (blockIdx.x == 0 && threadIdx.x < 4) {
        long i = threadIdx.x < 3 ? (long)threadIdx.x : NTOT - 1;
        int s = (int)(i >> 7) & (SEQ - 1);
        if (s != pos) { oa[i] = a[i]; ob[i] = b[i]; }
    }
}

// ---------------- QKV GEMV (256 blocks), PDL: prefetch -> sync -> fma ------
__global__ void __launch_bounds__(256, 1) k_qkv(
    const float* __restrict__ lnw,
    const float* __restrict__ Wq, const float* __restrict__ Wk,
    const float* __restrict__ Wv, int first,
    const float* __restrict__ emb, const int* __restrict__ ids)
{
    cudaTriggerProgrammaticLaunchCompletion();
    int bid = blockIdx.x, tid = threadIdx.x;
    int ct = bid & 3, rs = bid >> 2, r0 = rs * 16;
    int j = ct * 1024 + tid * 4;
    const float* W; int cols, jj;
    if (j < 2048)      { W = Wq; cols = 2048; jj = j; }
    else if (j < 3072) { W = Wk; cols = 1024; jj = j - 2048; }
    else               { W = Wv; cols = 1024; jj = j - 3072; }
    const float* p = W + (long)r0 * cols + jj;
    float4 wv[16];
    #pragma unroll
    for (int r = 0; r < 16; ++r) wv[r] = *(const float4*)(p + (long)r * cols);
    cudaGridDependencySynchronize();
    __shared__ float sm[9];
    __shared__ float sh_n[16];
    const float* src = first ? (emb + (long)ids[0] * DM) : g_x;
    float rstd = block_rstd_src(src, tid, sm);
    if (first && bid == 0)
        ((float4*)g_x)[tid] = ((const float4*)src)[tid];
    if (tid < 16) sh_n[tid] = src[r0 + tid] * rstd * lnw[r0 + tid];
    __syncthreads();
    float4 acc = {0.f,0.f,0.f,0.f};
    #pragma unroll
    for (int r = 0; r < 16; ++r) fma4(acc, sh_n[r], wv[r]);
    *(float4*)&g_qkv_part[rs][j] = acc;
}

// ---------------- attention (256 blocks), PDL sync at top ------------------
__global__ void __launch_bounds__(256) k_attn(
    const float* __restrict__ pk, const float* __restrict__ pv,
    const int* __restrict__ stepp, const int* __restrict__ plen, int layer,
    float* __restrict__ ok, float* __restrict__ ov)
{
    cudaTriggerProgrammaticLaunchCompletion();
    int bid = blockIdx.x, tid = threadIdx.x;
    int pos = stepp[0] + plen[0];
    __shared__ __align__(16) float shq[2*DH];
    __shared__ __align__(16) float shk[DH];
    __shared__ __align__(16) float shv[DH];
    __shared__ float shs[2*128];
    __shared__ float red[8];
    __shared__ float shm[2];
    int kv = bid & 7, ch = bid >> 3;
    int s0 = ch << 7;
    if (s0 > pos) {
        if (tid < 2) g_attn_l[kv][ch][tid] = 0.f;   // 0 over 0: value-stable
        return;
    }
    cudaGridDependencySynchronize();
    int smax = (pos < s0 + 127) ? pos : s0 + 127;
    bool haspos = (ch == (pos >> 7));
    {
        int h = tid >> 7, d = tid & 127;
        float a = 0.f;
        #pragma unroll 16
        for (int i = 0; i < NPQ; ++i) a += g_qkv_part[i][(kv*2 + h)*DH + d];
        shq[h*DH + d] = a;
    }
    if (haspos) {
        int off = (tid < 128) ? (2048 + kv*DH + tid) : (3072 + kv*DH + tid - 128);
        float a = 0.f;
        #pragma unroll 16
        for (int i = 0; i < NPQ; ++i) a += g_qkv_part[i][off];
        if (tid < 128) shk[tid] = a; else shv[tid - 128] = a;
    }
    __syncthreads();
    const float SCALE = 0.08838834764831845f;   // 1/sqrt(128)
    const float LF = 0.14391156831212785f;      // ln(10000)/64
    if (tid < 128) {
        int h = tid >> 6, i = tid & 63;
        float ang = (float)pos * expf(-(float)i * LF);
        float c, s; sincosf(ang, &s, &c);
        float x1 = shq[h*128 + i], x2 = shq[h*128 + i + 64];
        shq[h*128 + i]      = (x1*c - x2*s) * SCALE;
        shq[h*128 + i + 64] = (x2*c + x1*s) * SCALE;
    } else if (haspos && tid < 192) {
        int i = tid - 128;
        float ang = (float)pos * expf(-(float)i * LF);
        float c, s; sincosf(ang, &s, &c);
        float k1 = shk[i], k2 = shk[i + 64];
        shk[i]      = k1*c - k2*s;
        shk[i + 64] = k2*c + k1*s;
    }
    __syncthreads();
    if (haspos) {
        long rb = (((long)layer * NKV + kv) * SEQ + pos) * DH;
        if (tid < 128) ok[rb + tid] = shk[tid];
        else           ov[rb + tid - 128] = shv[tid - 128];
    }
    int warp = tid >> 5, lane = tid & 31;
    float4 q0 = ((const float4*)shq)[lane];
    float4 q1 = ((const float4*)(shq + 128))[lane];
    long kb = ((long)layer * NKV + kv) * SEQ * DH;
    #pragma unroll 2
    for (int it = 0; it < 16; ++it) {
        int sl = (it << 3) + warp;
        int si = s0 + sl;
        if (si <= smax) {
            float4 kk;
            if (si == pos) kk = ((const float4*)shk)[lane];
            else           kk = *(const float4*)(pk + kb + (long)si*DH + lane*4);
            float d0 = q0.x*kk.x + q0.y*kk.y + q0.z*kk.z + q0.w*kk.w;
            float d1 = q1.x*kk.x + q1.y*kk.y + q1.z*kk.z + q1.w*kk.w;
            #pragma unroll
            for (int o = 16; o > 0; o >>= 1) {
                d0 += __shfl_down_sync(0xffffffffu, d0, o);
                d1 += __shfl_down_sync(0xffffffffu, d1, o);
            }
            if (lane == 0) { shs[sl] = d0; shs[128 + sl] = d1; }
        } else if (lane == 0) {
            shs[sl] = -1e30f; shs[128 + sl] = -1e30f;
        }
    }
    __syncthreads();
    int h = tid >> 7, d = tid & 127;
    float v = shs[h*128 + d];
    float m = v;
    #pragma unroll
    for (int o = 16; o > 0; o >>= 1) m = fmaxf(m, __shfl_down_sync(0xffffffffu, m, o));
    if (lane == 0) red[warp] = m;
    __syncthreads();
    if (tid < 2)
        shm[tid] = fmaxf(fmaxf(red[tid*4], red[tid*4+1]), fmaxf(red[tid*4+2], red[tid*4+3]));
    __syncthreads();
    float p = expf(v - shm[h]);
    shs[h*128 + d] = p;
    float l = p;
    #pragma unroll
    for (int o = 16; o > 0; o >>= 1) l += __shfl_down_sync(0xffffffffu, l, o);
    if (lane == 0) red[warp] = l;
    __syncthreads();
    if (tid < 2) {
        g_attn_m[kv][ch][tid] = shm[tid];
        g_attn_l[kv][ch][tid] = red[tid*4] + red[tid*4+1] + red[tid*4+2] + red[tid*4+3];
    }
    int count = smax - s0 + 1;
    int nglob = haspos ? count - 1 : count;
    const float* pvp = pv + kb + (long)s0*DH + d;
    float acc = 0.f;
    int s = 0;
    for (; s + 7 < nglob; s += 8) {
        float acc2 = 0.f;
        #pragma unroll
        for (int u = 0; u < 8; u += 2) {
            acc  += shs[h*128 + s+u]   * pvp[(long)(s+u)*DH];
            acc2 += shs[h*128 + s+u+1] * pvp[(long)(s+u+1)*DH];
        }
        acc += acc2;
    }
    for (; s < nglob; ++s) acc += shs[h*128 + s] * pvp[(long)s*DH];
    if (haspos) acc += shs[h*128 + count - 1] * shv[d];
    g_attn_o[kv][ch][h][d] = acc;
}

// ---------------- Wo GEMV (128 blocks), PDL + parallel combine -------------
__global__ void __launch_bounds__(256, 1) k_wo(const float* __restrict__ Wo)
{
    cudaTriggerProgrammaticLaunchCompletion();
    int bid = blockIdx.x, tid = threadIdx.x;
    int r0 = bid * 16;
    int j = tid * 4;
    const float* pw = Wo + (long)r0 * DM + j;
    float4 wv[16];
    #pragma unroll
    for (int r = 0; r < 16; ++r) wv[r] = *(const float4*)(pw + (long)r * DM);
    cudaGridDependencySynchronize();
    __shared__ float shw[NCH];
    __shared__ float pr[128];
    __shared__ float av[16];
    __shared__ float idn;
    int p = r0 >> 7, kv = p >> 1, hh = p & 1, db = r0 & 127;
    if (tid < 32) {
        float m = g_attn_m[kv][tid][hh];
        float l = g_attn_l[kv][tid][hh];
        float mm = (l > 0.f) ? m : -1e30f;
        float M = mm;
        #pragma unroll
        for (int o = 16; o > 0; o >>= 1) M = fmaxf(M, __shfl_xor_sync(0xffffffffu, M, o));
        float w = (l > 0.f) ? expf(m - M) : 0.f;
        float dl = w * l;
        #pragma unroll
        for (int o = 16; o > 0; o >>= 1) dl += __shfl_xor_sync(0xffffffffu, dl, o);
        shw[tid] = w;
        if (tid == 0) idn = 1.f / dl;
    }
    __syncthreads();
    if (tid < 128) {
        int row = tid & 15, grp = tid >> 4;   // 8 groups x 4 chunks
        float s = 0.f;
        #pragma unroll
        for (int c = 0; c < 4; ++c) {
            int ch = grp * 4 + c;
            s += shw[ch] * g_attn_o[kv][ch][hh][db + row];
        }
        pr[tid] = s;
    }
    __syncthreads();
    if (tid < 16) {
        float s = 0.f;
        #pragma unroll
        for (int g2 = 0; g2 < 8; ++g2) s += pr[g2 * 16 + tid];
        av[tid] = s * idn;
    }
    __syncthreads();
    float4 acc = {0.f,0.f,0.f,0.f};
    #pragma unroll
    for (int r = 0; r < 16; ++r) fma4(acc, av[r], wv[r]);
    atomicAdd(&g_x[j],     acc.x);
    atomicAdd(&g_x[j + 1], acc.y);
    atomicAdd(&g_x[j + 2], acc.z);
    atomicAdd(&g_x[j + 3], acc.w);
}

// ---------------- gate/up GEMV (512 blocks), PDL ---------------------------
__global__ void __launch_bounds__(256, 1) k_gateup(
    const float* __restrict__ lnw,
    const float* __restrict__ Wg, const float* __restrict__ Wu)
{
    cudaTriggerProgrammaticLaunchCompletion();
    int bid = blockIdx.x, tid = threadIdx.x;
    int ct = bid & 7, rs = bid >> 3, r0 = rs * 16;
    int j = ct * 1024 + tid * 4;
    const float* W; int jj;
    if (j < FF) { W = Wg; jj = j; } else { W = Wu; jj = j - FF; }
    const float* p = W + (long)r0 * FF + jj;
    float4 wv[16];
    #pragma unroll
    for (int r = 0; r < 16; ++r) wv[r] = *(const float4*)(p + (long)r * FF);
    cudaGridDependencySynchronize();
    __shared__ float sm[9];
    __shared__ float sh_n[16];
    float rstd = block_rstd_src(g_x, tid, sm);
    if (tid < 16) sh_n[tid] = g_x[r0 + tid] * rstd * lnw[r0 + tid];
    __syncthreads();
    float4 acc = {0.f,0.f,0.f,0.f};
    #pragma unroll
    for (int r = 0; r < 16; ++r) fma4(acc, sh_n[r], wv[r]);
    *(float4*)&g_gu_part[rs][j] = acc;
}

// ---------------- Wd GEMV (256 blocks), PDL --------------------------------
__global__ void __launch_bounds__(256, 1) k_wd(const float* __restrict__ Wd)
{
    cudaTriggerProgrammaticLaunchCompletion();
    int bid = blockIdx.x, tid = threadIdx.x;
    int r0 = bid * 16;
    int j = tid * 4;
    const float* pw = Wd + (long)r0 * DM + j;
    float4 wv[16];
    #pragma unroll
    for (int r = 0; r < 16; ++r) wv[r] = *(const float4*)(pw + (long)r * DM);
    cudaGridDependencySynchronize();
    __shared__ float sh_g[64], sh_u[64];
    __shared__ float sh_h[16];
    if (tid < 64) {
        int row = tid & 15, grp = tid >> 4;
        float g = 0.f, u = 0.f;
        #pragma unroll
        for (int i = 0; i < 16; ++i) {
            int pi = grp * 16 + i;
            g += g_gu_part[pi][r0 + row];
            u += g_gu_part[pi][FF + r0 + row];
        }
        sh_g[tid] = g; sh_u[tid] = u;
    }
    __syncthreads();
    if (tid < 16) {
        float g = sh_g[tid] + sh_g[16 + tid] + sh_g[32 + tid] + sh_g[48 + tid];
        float u = sh_u[tid] + sh_u[16 + tid] + sh_u[32 + tid] + sh_u[48 + tid];
        sh_h[tid] = (g / (1.f + expf(-g))) * u;
    }
    __syncthreads();
    float4 acc = {0.f,0.f,0.f,0.f};
    #pragma unroll
    for (int r = 0; r < 16; ++r) fma4(acc, sh_h[r], wv[r]);
    atomicAdd(&g_x[j],     acc.x);
    atomicAdd(&g_x[j + 1], acc.y);
    atomicAdd(&g_x[j + 2], acc.z);
    atomicAdd(&g_x[j + 3], acc.w);
}

// ---------------- LM head GEMV (plain launch) ------------------------------
__global__ void __launch_bounds__(256, 1) k_lm(
    const float* __restrict__ lnf, const float* __restrict__ Wlm)
{
    __shared__ float sm[9];
    __shared__ float n[64];
    int tid = threadIdx.x;
    float rstd = block_rstd_src(g_x, tid, sm);
    int r0 = blockIdx.y * 64;
    if (tid < 64) n[tid] = g_x[r0 + tid] * rstd * lnf[r0 + tid];
    __syncthreads();
    int j = blockIdx.x * 1024 + tid * 4;
    if (j >= VOC) return;
    float4 acc = {0.f,0.f,0.f,0.f};
    #pragma unroll
    for (int c = 0; c < 4; ++c) {
        const float* p = Wlm + ((long)r0 + c*16) * VOC + j;
        float4 wv[16];
        #pragma unroll
        for (int r = 0; r < 16; ++r) wv[r] = *(const float4*)(p + (long)r * VOC);
        #pragma unroll
        for (int r = 0; r < 16; ++r) fma4(acc, n[c*16 + r], wv[r]);
    }
    *(float4*)&g_lm_part[blockIdx.y][j] = acc;
}

// ---------------- argmax ----------------
__global__ void __launch_bounds__(256) k_amax1()
{
    __shared__ float sv[256];
    __shared__ int   si[256];
    int t = threadIdx.x;
    int j = blockIdx.x * 256 + t;
    float v = 0.f;
    #pragma unroll
    for (int i = 0; i < NPL; ++i) v += g_lm_part[i][j];
    sv[t] = v; si[t] = j;
    __syncthreads();
    for (int o = 128; o > 0; o >>= 1) {
        if (t < o) {
            float v2 = sv[t + o]; int i2 = si[t + o];
            if (v2 > sv[t] || (v2 == sv[t] && i2 < si[t])) { sv[t] = v2; si[t] = i2; }
        }
        __syncthreads();
    }
    if (t == 0) { g_amax_val[blockIdx.x] = sv[0]; g_amax_idx[blockIdx.x] = si[0]; }
}

__global__ void __launch_bounds__(128) k_amax2(float* __restrict__ out)
{
    __shared__ float sv[128];
    __shared__ int   si[128];
    int t = threadIdx.x;
    if (t < 125) { sv[t] = g_amax_val[t]; si[t] = g_amax_idx[t]; }
    else         { sv[t] = -1e38f;        si[t] = 0x7fffffff; }
    __syncthreads();
    for (int o = 64; o > 0; o >>= 1) {
        if (t < o) {
            float v2 = sv[t + o]; int i2 = si[t + o];
            if (v2 > sv[t] || (v2 == sv[t] && i2 < si[t])) { sv[t] = v2; si[t] = i2; }
        }
        __syncthreads();
    }
    if (t == 0) out[0] = (float)si[0];
}

// ---------------- launch ----------------
extern "C" void kernel_launch(void* const* d_in, const int* in_sizes, int n_in,
                              void* d_out, int out_size)
{
    const int*   ids  = (const int*)  d_in[0];
    const int*   step = (const int*)  d_in[1];
    const int*   plen = (const int*)  d_in[2];
    const float* pk   = (const float*)d_in[3];
    const float* pv   = (const float*)d_in[4];
    const float* emb  = (const float*)d_in[5];
    const float* Wq   = (const float*)d_in[6];
    const float* Wk   = (const float*)d_in[7];
    const float* Wv   = (const float*)d_in[8];
    const float* Wo   = (const float*)d_in[9];
    const float* Wg   = (const float*)d_in[10];
    const float* Wu   = (const float*)d_in[11];
    const float* Wd   = (const float*)d_in[12];
    const float* ln1  = (const float*)d_in[13];
    const float* ln2  = (const float*)d_in[14];
    const float* lnf  = (const float*)d_in[15];
    const float* Wlm  = (const float*)d_in[16];

    float* out = (float*)d_out;
    const long CACHE = (long)NL * NKV * SEQ * DH;
    float* ok = out + 1;
    float* ov = out + 1 + CACHE;

    // fork a parallel branch for the cache copy
    cudaStream_t s2;
    cudaStreamCreateWithFlags(&s2, cudaStreamNonBlocking);
    cudaEvent_t eF, eJ;
    cudaEventCreateWithFlags(&eF, cudaEventDisableTiming);
    cudaEventCreateWithFlags(&eJ, cudaEventDisableTiming);
    cudaEventRecord(eF, 0);
    cudaStreamWaitEvent(s2, eF, 0);
    k_copy2<<<2048, 256, 0, s2>>>(pk, pv, ok, ov, step, plen);
    cudaEventRecord(eJ, s2);

    // PDL launch config for the serial chain
    cudaLaunchConfig_t cfg = {};
    cudaLaunchAttribute at[1];
    at[0].id = cudaLaunchAttributeProgrammaticStreamSerialization;
    at[0].val.programmaticStreamSerializationAllowed = 1;
    cfg.attrs = at;
    cfg.numAttrs = 1;
    cfg.blockDim = dim3(256, 1, 1);
    cfg.stream = 0;

    for (int l = 0; l < NL; ++l) {
        const float* lnwp = ln1 + (long)l * DM;
        const float* wqp = Wq + (long)l * DM * 2048;
        const float* wkp = Wk + (long)l * DM * 1024;
        const float* wvp = Wv + (long)l * DM * 1024;
        const float* wop = Wo + (long)l * 2048 * DM;
        const float* ln2p = ln2 + (long)l * DM;
        const float* wgp = Wg + (long)l * DM * FF;
        const float* wup = Wu + (long)l * DM * FF;
        const float* wdp = Wd + (long)l * FF * DM;
        int first = (l == 0) ? 1 : 0;

        cfg.gridDim = dim3(256, 1, 1);
        cudaLaunchKernelEx(&cfg, k_qkv, lnwp, wqp, wkp, wvp, first, emb, ids);
        cfg.gridDim = dim3(256, 1, 1);
        cudaLaunchKernelEx(&cfg, k_attn, pk, pv, step, plen, l, ok, ov);
        cfg.gridDim = dim3(128, 1, 1);
        cudaLaunchKernelEx(&cfg, k_wo, wop);
        cfg.gridDim = dim3(512, 1, 1);
        cudaLaunchKernelEx(&cfg, k_gateup, ln2p, wgp, wup);
        cfg.gridDim = dim3(256, 1, 1);
        cudaLaunchKernelEx(&cfg, k_wd, wdp);
    }

    // join the copy branch before the tail
    cudaStreamWaitEvent(0, eJ, 0);

    k_lm<<<dim3(32, NPL), 256>>>(lnf, Wlm);
    k_amax1<<<125, 256>>>();
    k_amax2<<<1, 128>>>(out);

    cudaEventDestroy(eF);
    cudaEventDestroy(eJ);
    cudaStreamDestroy(s2);
}

// round 16
// speedup vs baseline: 1.1220x; 1.1220x over previous
#include <cuda_runtime.h>

// ---------------- problem constants ----------------
#define NL   16
#define DM   1024
#define NH   16
#define NKV  8
#define DH   128
#define SEQ  4096
#define FF   4096
#define VOC  32000

#define NPQ  64    // qkv row partials (16 rows each)
#define NPG  64    // gate/up row partials (16 rows each)
#define NPL  16    // lm row partials (64 rows each)
#define NCH  32    // attention chunks of 128

#define NTOT 67108864L              // cache elements per tensor
#define TQ   16777215L              // dest quads ((N-3)>>2)

// ---------------- scratch ----------------
__device__ __align__(16) float g_x[DM];
__device__ __align__(16) float g_qkv_part[NPQ][4096];
__device__ float g_attn_m[NKV][NCH][2];
__device__ float g_attn_l[NKV][NCH][2];
__device__ __align__(16) float g_attn_o[NKV][NCH][2][DH];
__device__ __align__(16) float g_gu_part[NPG][2*FF];
__device__ __align__(16) float g_lm_part[NPL][VOC];
__device__ float g_amax_val[128];
__device__ int   g_amax_idx[128];

__device__ __forceinline__ void fma4(float4& acc, float a, const float4& w) {
    acc.x += a * w.x; acc.y += a * w.y; acc.z += a * w.z; acc.w += a * w.w;
}

__device__ __forceinline__ void pf(const float* p) {
    asm volatile("prefetch.global.L2 [%0];" :: "l"(p));
}

// Block rmsnorm rstd from src[DM] (256 threads). Uses sm[0..8].
__device__ __forceinline__ float block_rstd_src(const float* __restrict__ src,
                                                int tid, float* sm) {
    float4 xv = ((const float4*)src)[tid];
    float ss = xv.x*xv.x + xv.y*xv.y + xv.z*xv.z + xv.w*xv.w;
    #pragma unroll
    for (int o = 16; o > 0; o >>= 1) ss += __shfl_down_sync(0xffffffffu, ss, o);
    if ((tid & 31) == 0) sm[tid >> 5] = ss;
    __syncthreads();
    if (tid == 0) {
        float t = 0.f;
        #pragma unroll
        for (int i = 0; i < 8; ++i) t += sm[i];
        sm[8] = rsqrtf(t * (1.0f / DM) + 1e-6f);
    }
    __syncthreads();
    return sm[8];
}

// ---------------- KV cache copy (parallel stream; skips ALL rows at pos) ---
__global__ void k_copy2(const float* __restrict__ a, const float* __restrict__ b,
                        float* __restrict__ oa, float* __restrict__ ob,
                        const int* __restrict__ stepp, const int* __restrict__ plen)
{
    int pos = stepp[0] + plen[0];
    const float4* a4 = (const float4*)a;
    const float4* b4 = (const float4*)b;
    float4* oa4 = (float4*)(oa + 3);
    float4* ob4 = (float4*)(ob + 3);
    long t = (long)blockIdx.x * blockDim.x + threadIdx.x;
    long st = (long)gridDim.x * blockDim.x;
    for (; t < TQ; t += st) {
        long e0 = 4*t + 3;
        int s0 = (int)(e0 >> 7) & (SEQ - 1);
        int s1 = (int)((e0 + 3) >> 7) & (SEQ - 1);
        float4 A = a4[t], B = a4[t + 1];
        float4 r; r.x = A.w; r.y = B.x; r.z = B.y; r.w = B.z;
        if (s0 != pos && s1 != pos) {
            __stcs(oa4 + t, r);
            A = b4[t]; B = b4[t + 1];
            r.x = A.w; r.y = B.x; r.z = B.y; r.w = B.z;
            __stcs(ob4 + t, r);
        } else {
            float ra[4] = {A.w, B.x, B.y, B.z};
            A = b4[t]; B = b4[t + 1];
            float rb[4] = {A.w, B.x, B.y, B.z};
            #pragma unroll
            for (int k = 0; k < 4; ++k) {
                long e = e0 + k;
                if ((((int)(e >> 7)) & (SEQ - 1)) != pos) {
                    oa[e] = ra[k]; ob[e] = rb[k];
                }
            }
        }
    }
    if (blockIdx.x == 0 && threadIdx.x < 4) {
        long i = threadIdx.x < 3 ? (long)threadIdx.x : NTOT - 1;
        int s = (int)(i >> 7) & (SEQ - 1);
        if (s != pos) { oa[i] = a[i]; ob[i] = b[i]; }
    }
}

// ---------------- QKV GEMV (256 blocks): burst -> prefetch KV -> sync ------
__global__ void __launch_bounds__(256, 1) k_qkv(
    const float* __restrict__ lnw,
    const float* __restrict__ Wq, const float* __restrict__ Wk,
    const float* __restrict__ Wv, int first,
    const float* __restrict__ emb, const int* __restrict__ ids,
    const int* __restrict__ stepp, const int* __restrict__ plen,
    const float* __restrict__ pkl, const float* __restrict__ pvl)
{
    cudaTriggerProgrammaticLaunchCompletion();
    int bid = blockIdx.x, tid = threadIdx.x;
    int ct = bid & 3, rs = bid >> 2, r0 = rs * 16;
    int j = ct * 1024 + tid * 4;
    const float* W; int cols, jj;
    if (j < 2048)      { W = Wq; cols = 2048; jj = j; }
    else if (j < 3072) { W = Wk; cols = 1024; jj = j - 2048; }
    else               { W = Wv; cols = 1024; jj = j - 3072; }
    const float* p = W + (long)r0 * cols + jj;
    float4 wv[16];
    #pragma unroll
    for (int r = 0; r < 16; ++r) wv[r] = *(const float4*)(p + (long)r * cols);
    // prefetch this layer's K/V cache rows [0, pos] into L2 for k_attn
    {
        int pos = stepp[0] + plen[0];
        int gid = bid * 256 + tid;               // 0..65535
        int lph = (pos + 1) * 4;                 // 128B lines per head
        #pragma unroll
        for (int kv = 0; kv < NKV; ++kv) {
            const float* kb = pkl + (long)kv * SEQ * DH;
            const float* vb = pvl + (long)kv * SEQ * DH;
            for (int i = gid; i < lph; i += 65536) {
                pf(kb + (long)i * 32);
                pf(vb + (long)i * 32);
            }
        }
    }
    cudaGridDependencySynchronize();
    __shared__ float sm[9];
    __shared__ float sh_n[16];
    const float* src = first ? (emb + (long)ids[0] * DM) : g_x;
    float rstd = block_rstd_src(src, tid, sm);
    if (first && bid == 0)
        ((float4*)g_x)[tid] = ((const float4*)src)[tid];
    if (tid < 16) sh_n[tid] = src[r0 + tid] * rstd * lnw[r0 + tid];
    __syncthreads();
    float4 acc = {0.f,0.f,0.f,0.f};
    #pragma unroll
    for (int r = 0; r < 16; ++r) fma4(acc, sh_n[r], wv[r]);
    *(float4*)&g_qkv_part[rs][j] = acc;
}

// ---------------- attention (256 blocks): prefetch Wo, then flash-decode ---
__global__ void __launch_bounds__(256) k_attn(
    const float* __restrict__ pk, const float* __restrict__ pv,
    const int* __restrict__ stepp, const int* __restrict__ plen, int layer,
    float* __restrict__ ok, float* __restrict__ ov,
    const float* __restrict__ wo_next)
{
    cudaTriggerProgrammaticLaunchCompletion();
    int bid = blockIdx.x, tid = threadIdx.x;
    int pos = stepp[0] + plen[0];
    // prefetch Wo (65536 lines over 65536 threads) before any early exit
    pf(wo_next + (long)(bid * 256 + tid) * 32);
    __shared__ __align__(16) float shq[2*DH];
    __shared__ __align__(16) float shk[DH];
    __shared__ __align__(16) float shv[DH];
    __shared__ float shs[2*128];
    __shared__ float red[8];
    __shared__ float shm[2];
    int kv = bid & 7, ch = bid >> 3;
    int s0 = ch << 7;
    if (s0 > pos) {
        if (tid < 2) g_attn_l[kv][ch][tid] = 0.f;   // 0 over 0: value-stable
        return;
    }
    cudaGridDependencySynchronize();
    int smax = (pos < s0 + 127) ? pos : s0 + 127;
    bool haspos = (ch == (pos >> 7));
    {
        int h = tid >> 7, d = tid & 127;
        float a = 0.f;
        #pragma unroll 16
        for (int i = 0; i < NPQ; ++i) a += g_qkv_part[i][(kv*2 + h)*DH + d];
        shq[h*DH + d] = a;
    }
    if (haspos) {
        int off = (tid < 128) ? (2048 + kv*DH + tid) : (3072 + kv*DH + tid - 128);
        float a = 0.f;
        #pragma unroll 16
        for (int i = 0; i < NPQ; ++i) a += g_qkv_part[i][off];
        if (tid < 128) shk[tid] = a; else shv[tid - 128] = a;
    }
    __syncthreads();
    const float SCALE = 0.08838834764831845f;   // 1/sqrt(128)
    const float LF = 0.14391156831212785f;      // ln(10000)/64
    if (tid < 128) {
        int h = tid >> 6, i = tid & 63;
        float ang = (float)pos * expf(-(float)i * LF);
        float c, s; sincosf(ang, &s, &c);
        float x1 = shq[h*128 + i], x2 = shq[h*128 + i + 64];
        shq[h*128 + i]      = (x1*c - x2*s) * SCALE;
        shq[h*128 + i + 64] = (x2*c + x1*s) * SCALE;
    } else if (haspos && tid < 192) {
        int i = tid - 128;
        float ang = (float)pos * expf(-(float)i * LF);
        float c, s; sincosf(ang, &s, &c);
        float k1 = shk[i], k2 = shk[i + 64];
        shk[i]      = k1*c - k2*s;
        shk[i + 64] = k2*c + k1*s;
    }
    __syncthreads();
    if (haspos) {
        long rb = (((long)layer * NKV + kv) * SEQ + pos) * DH;
        if (tid < 128) ok[rb + tid] = shk[tid];
        else           ov[rb + tid - 128] = shv[tid - 128];
    }
    int warp = tid >> 5, lane = tid & 31;
    float4 q0 = ((const float4*)shq)[lane];
    float4 q1 = ((const float4*)(shq + 128))[lane];
    long kb = ((long)layer * NKV + kv) * SEQ * DH;
    #pragma unroll 2
    for (int it = 0; it < 16; ++it) {
        int sl = (it << 3) + warp;
        int si = s0 + sl;
        if (si <= smax) {
            float4 kk;
            if (si == pos) kk = ((const float4*)shk)[lane];
            else           kk = *(const float4*)(pk + kb + (long)si*DH + lane*4);
            float d0 = q0.x*kk.x + q0.y*kk.y + q0.z*kk.z + q0.w*kk.w;
            float d1 = q1.x*kk.x + q1.y*kk.y + q1.z*kk.z + q1.w*kk.w;
            #pragma unroll
            for (int o = 16; o > 0; o >>= 1) {
                d0 += __shfl_down_sync(0xffffffffu, d0, o);
                d1 += __shfl_down_sync(0xffffffffu, d1, o);
            }
            if (lane == 0) { shs[sl] = d0; shs[128 + sl] = d1; }
        } else if (lane == 0) {
            shs[sl] = -1e30f; shs[128 + sl] = -1e30f;
        }
    }
    __syncthreads();
    int h = tid >> 7, d = tid & 127;
    float v = shs[h*128 + d];
    float m = v;
    #pragma unroll
    for (int o = 16; o > 0; o >>= 1) m = fmaxf(m, __shfl_down_sync(0xffffffffu, m, o));
    if (lane == 0) red[warp] = m;
    __syncthreads();
    if (tid < 2)
        shm[tid] = fmaxf(fmaxf(red[tid*4], red[tid*4+1]), fmaxf(red[tid*4+2], red[tid*4+3]));
    __syncthreads();
    float p = expf(v - shm[h]);
    shs[h*128 + d] = p;
    float l = p;
    #pragma unroll
    for (int o = 16; o > 0; o >>= 1) l += __shfl_down_sync(0xffffffffu, l, o);
    if (lane == 0) red[warp] = l;
    __syncthreads();
    if (tid < 2) {
        g_attn_m[kv][ch][tid] = shm[tid];
        g_attn_l[kv][ch][tid] = red[tid*4] + red[tid*4+1] + red[tid*4+2] + red[tid*4+3];
    }
    int count = smax - s0 + 1;
    int nglob = haspos ? count - 1 : count;
    const float* pvp = pv + kb + (long)s0*DH + d;
    float acc = 0.f;
    int s = 0;
    for (; s + 7 < nglob; s += 8) {
        float acc2 = 0.f;
        #pragma unroll
        for (int u = 0; u < 8; u += 2) {
            acc  += shs[h*128 + s+u]   * pvp[(long)(s+u)*DH];
            acc2 += shs[h*128 + s+u+1] * pvp[(long)(s+u+1)*DH];
        }
        acc += acc2;
    }
    for (; s < nglob; ++s) acc += shs[h*128 + s] * pvp[(long)s*DH];
    if (haspos) acc += shs[h*128 + count - 1] * shv[d];
    g_attn_o[kv][ch][h][d] = acc;
}

// ---------------- Wo GEMV (128 blocks): burst -> prefetch Wg/Wu -> combine -
__global__ void __launch_bounds__(256, 1) k_wo(
    const float* __restrict__ Wo,
    const float* __restrict__ wg_next, const float* __restrict__ wu_next)
{
    cudaTriggerProgrammaticLaunchCompletion();
    int bid = blockIdx.x, tid = threadIdx.x;
    int r0 = bid * 16;
    int j = tid * 4;
    const float* pw = Wo + (long)r0 * DM + j;
    float4 wv[16];
    #pragma unroll
    for (int r = 0; r < 16; ++r) wv[r] = *(const float4*)(pw + (long)r * DM);
    // prefetch gate/up weights: 131072 lines each over 32768 threads
    {
        int gid = bid * 256 + tid;
        #pragma unroll
        for (int i = 0; i < 4; ++i) {
            pf(wg_next + (long)(gid + i * 32768) * 32);
            pf(wu_next + (long)(gid + i * 32768) * 32);
        }
    }
    cudaGridDependencySynchronize();
    __shared__ float shw[NCH];
    __shared__ float pr[128];
    __shared__ float av[16];
    __shared__ float idn;
    int p = r0 >> 7, kv = p >> 1, hh = p & 1, db = r0 & 127;
    if (tid < 32) {
        float m = g_attn_m[kv][tid][hh];
        float l = g_attn_l[kv][tid][hh];
        float mm = (l > 0.f) ? m : -1e30f;
        float M = mm;
        #pragma unroll
        for (int o = 16; o > 0; o >>= 1) M = fmaxf(M, __shfl_xor_sync(0xffffffffu, M, o));
        float w = (l > 0.f) ? expf(m - M) : 0.f;
        float dl = w * l;
        #pragma unroll
        for (int o = 16; o > 0; o >>= 1) dl += __shfl_xor_sync(0xffffffffu, dl, o);
        shw[tid] = w;
        if (tid == 0) idn = 1.f / dl;
    }
    __syncthreads();
    if (tid < 128) {
        int row = tid & 15, grp = tid >> 4;   // 8 groups x 4 chunks
        float s = 0.f;
        #pragma unroll
        for (int c = 0; c < 4; ++c) {
            int ch = grp * 4 + c;
            s += shw[ch] * g_attn_o[kv][ch][hh][db + row];
        }
        pr[tid] = s;
    }
    __syncthreads();
    if (tid < 16) {
        float s = 0.f;
        #pragma unroll
        for (int g2 = 0; g2 < 8; ++g2) s += pr[g2 * 16 + tid];
        av[tid] = s * idn;
    }
    __syncthreads();
    float4 acc = {0.f,0.f,0.f,0.f};
    #pragma unroll
    for (int r = 0; r < 16; ++r) fma4(acc, av[r], wv[r]);
    atomicAdd(&g_x[j],     acc.x);
    atomicAdd(&g_x[j + 1], acc.y);
    atomicAdd(&g_x[j + 2], acc.z);
    atomicAdd(&g_x[j + 3], acc.w);
}

// ---------------- gate/up GEMV (512 blocks): burst -> prefetch Wd ----------
__global__ void __launch_bounds__(256, 1) k_gateup(
    const float* __restrict__ lnw,
    const float* __restrict__ Wg, const float* __restrict__ Wu,
    const float* __restrict__ wd_next)
{
    cudaTriggerProgrammaticLaunchCompletion();
    int bid = blockIdx.x, tid = threadIdx.x;
    int ct = bid & 7, rs = bid >> 3, r0 = rs * 16;
    int j = ct * 1024 + tid * 4;
    const float* W; int jj;
    if (j < FF) { W = Wg; jj = j; } else { W = Wu; jj = j - FF; }
    const float* p = W + (long)r0 * FF + jj;
    float4 wv[16];
    #pragma unroll
    for (int r = 0; r < 16; ++r) wv[r] = *(const float4*)(p + (long)r * FF);
    pf(wd_next + (long)(bid * 256 + tid) * 32);   // 131072 lines, 1/thread
    cudaGridDependencySynchronize();
    __shared__ float sm[9];
    __shared__ float sh_n[16];
    float rstd = block_rstd_src(g_x, tid, sm);
    if (tid < 16) sh_n[tid] = g_x[r0 + tid] * rstd * lnw[r0 + tid];
    __syncthreads();
    float4 acc = {0.f,0.f,0.f,0.f};
    #pragma unroll
    for (int r = 0; r < 16; ++r) fma4(acc, sh_n[r], wv[r]);
    *(float4*)&g_gu_part[rs][j] = acc;
}

// ---------------- Wd GEMV (256 blocks): burst -> prefetch next qkv ---------
__global__ void __launch_bounds__(256, 1) k_wd(
    const float* __restrict__ Wd,
    const float* __restrict__ wq_next, const float* __restrict__ wk_next,
    const float* __restrict__ wv_next)
{
    cudaTriggerProgrammaticLaunchCompletion();
    int bid = blockIdx.x, tid = threadIdx.x;
    int r0 = bid * 16;
    int j = tid * 4;
    const float* pw = Wd + (long)r0 * DM + j;
    float4 wv[16];
    #pragma unroll
    for (int r = 0; r < 16; ++r) wv[r] = *(const float4*)(pw + (long)r * DM);
    if (wq_next) {
        int gid = bid * 256 + tid;               // 0..65535
        pf(wq_next + (long)gid * 32);            // Wq: 65536 lines
        if (gid < 32768) pf(wk_next + (long)gid * 32);            // Wk
        else             pf(wv_next + (long)(gid - 32768) * 32);  // Wv
    }
    cudaGridDependencySynchronize();
    __shared__ float sh_g[64], sh_u[64];
    __shared__ float sh_h[16];
    if (tid < 64) {
        int row = tid & 15, grp = tid >> 4;
        float g = 0.f, u = 0.f;
        #pragma unroll
        for (int i = 0; i < 16; ++i) {
            int pi = grp * 16 + i;
            g += g_gu_part[pi][r0 + row];
            u += g_gu_part[pi][FF + r0 + row];
        }
        sh_g[tid] = g; sh_u[tid] = u;
    }
    __syncthreads();
    if (tid < 16) {
        float g = sh_g[tid] + sh_g[16 + tid] + sh_g[32 + tid] + sh_g[48 + tid];
        float u = sh_u[tid] + sh_u[16 + tid] + sh_u[32 + tid] + sh_u[48 + tid];
        sh_h[tid] = (g / (1.f + expf(-g))) * u;
    }
    __syncthreads();
    float4 acc = {0.f,0.f,0.f,0.f};
    #pragma unroll
    for (int r = 0; r < 16; ++r) fma4(acc, sh_h[r], wv[r]);
    atomicAdd(&g_x[j],     acc.x);
    atomicAdd(&g_x[j + 1], acc.y);
    atomicAdd(&g_x[j + 2], acc.z);
    atomicAdd(&g_x[j + 3], acc.w);
}

// ---------------- LM head GEMV (plain launch) ------------------------------
__global__ void __launch_bounds__(256, 1) k_lm(
    const float* __restrict__ lnf, const float* __restrict__ Wlm)
{
    __shared__ float sm[9];
    __shared__ float n[64];
    int tid = threadIdx.x;
    float rstd = block_rstd_src(g_x, tid, sm);
    int r0 = blockIdx.y * 64;
    if (tid < 64) n[tid] = g_x[r0 + tid] * rstd * lnf[r0 + tid];
    __syncthreads();
    int j = blockIdx.x * 1024 + tid * 4;
    if (j >= VOC) return;
    float4 acc = {0.f,0.f,0.f,0.f};
    #pragma unroll
    for (int c = 0; c < 4; ++c) {
        const float* p = Wlm + ((long)r0 + c*16) * VOC + j;
        float4 wv[16];
        #pragma unroll
        for (int r = 0; r < 16; ++r) wv[r] = *(const float4*)(p + (long)r * VOC);
        #pragma unroll
        for (int r = 0; r < 16; ++r) fma4(acc, n[c*16 + r], wv[r]);
    }
    *(float4*)&g_lm_part[blockIdx.y][j] = acc;
}

// ---------------- argmax ----------------
__global__ void __launch_bounds__(256) k_amax1()
{
    __shared__ float sv[256];
    __shared__ int   si[256];
    int t = threadIdx.x;
    int j = blockIdx.x * 256 + t;
    float v = 0.f;
    #pragma unroll
    for (int i = 0; i < NPL; ++i) v += g_lm_part[i][j];
    sv[t] = v; si[t] = j;
    __syncthreads();
    for (int o = 128; o > 0; o >>= 1) {
        if (t < o) {
            float v2 = sv[t + o]; int i2 = si[t + o];
            if (v2 > sv[t] || (v2 == sv[t] && i2 < si[t])) { sv[t] = v2; si[t] = i2; }
        }
        __syncthreads();
    }
    if (t == 0) { g_amax_val[blockIdx.x] = sv[0]; g_amax_idx[blockIdx.x] = si[0]; }
}

__global__ void __launch_bounds__(128) k_amax2(float* __restrict__ out)
{
    __shared__ float sv[128];
    __shared__ int   si[128];
    int t = threadIdx.x;
    if (t < 125) { sv[t] = g_amax_val[t]; si[t] = g_amax_idx[t]; }
    else         { sv[t] = -1e38f;        si[t] = 0x7fffffff; }
    __syncthreads();
    for (int o = 64; o > 0; o >>= 1) {
        if (t < o) {
            float v2 = sv[t + o]; int i2 = si[t + o];
            if (v2 > sv[t] || (v2 == sv[t] && i2 < si[t])) { sv[t] = v2; si[t] = i2; }
        }
        __syncthreads();
    }
    if (t == 0) out[0] = (float)si[0];
}

// ---------------- launch ----------------
extern "C" void kernel_launch(void* const* d_in, const int* in_sizes, int n_in,
                              void* d_out, int out_size)
{
    const int*   ids  = (const int*)  d_in[0];
    const int*   step = (const int*)  d_in[1];
    const int*   plen = (const int*)  d_in[2];
    const float* pk   = (const float*)d_in[3];
    const float* pv   = (const float*)d_in[4];
    const float* emb  = (const float*)d_in[5];
    const float* Wq   = (const float*)d_in[6];
    const float* Wk   = (const float*)d_in[7];
    const float* Wv   = (const float*)d_in[8];
    const float* Wo   = (const float*)d_in[9];
    const float* Wg   = (const float*)d_in[10];
    const float* Wu   = (const float*)d_in[11];
    const float* Wd   = (const float*)d_in[12];
    const float* ln1  = (const float*)d_in[13];
    const float* ln2  = (const float*)d_in[14];
    const float* lnf  = (const float*)d_in[15];
    const float* Wlm  = (const float*)d_in[16];

    float* out = (float*)d_out;
    const long CACHE = (long)NL * NKV * SEQ * DH;
    float* ok = out + 1;
    float* ov = out + 1 + CACHE;

    // fork a parallel branch for the cache copy
    cudaStream_t s2;
    cudaStreamCreateWithFlags(&s2, cudaStreamNonBlocking);
    cudaEvent_t eF, eJ;
    cudaEventCreateWithFlags(&eF, cudaEventDisableTiming);
    cudaEventCreateWithFlags(&eJ, cudaEventDisableTiming);
    cudaEventRecord(eF, 0);
    cudaStreamWaitEvent(s2, eF, 0);
    k_copy2<<<2048, 256, 0, s2>>>(pk, pv, ok, ov, step, plen);
    cudaEventRecord(eJ, s2);

    // PDL launch config for the serial chain
    cudaLaunchConfig_t cfg = {};
    cudaLaunchAttribute at[1];
    at[0].id = cudaLaunchAttributeProgrammaticStreamSerialization;
    at[0].val.programmaticStreamSerializationAllowed = 1;
    cfg.attrs = at;
    cfg.numAttrs = 1;
    cfg.blockDim = dim3(256, 1, 1);
    cfg.stream = 0;

    for (int l = 0; l < NL; ++l) {
        const float* lnwp = ln1 + (long)l * DM;
        const float* wqp = Wq + (long)l * DM * 2048;
        const float* wkp = Wk + (long)l * DM * 1024;
        const float* wvp = Wv + (long)l * DM * 1024;
        const float* wop = Wo + (long)l * 2048 * DM;
        const float* ln2p = ln2 + (long)l * DM;
        const float* wgp = Wg + (long)l * DM * FF;
        const float* wup = Wu + (long)l * DM * FF;
        const float* wdp = Wd + (long)l * FF * DM;
        const float* pkl = pk + (long)l * NKV * SEQ * DH;
        const float* pvl = pv + (long)l * NKV * SEQ * DH;
        const float* wqn = (l + 1 < NL) ? Wq + (long)(l+1) * DM * 2048 : nullptr;
        const float* wkn = (l + 1 < NL) ? Wk + (long)(l+1) * DM * 1024 : nullptr;
        const float* wvn = (l + 1 < NL) ? Wv + (long)(l+1) * DM * 1024 : nullptr;
        int first = (l == 0) ? 1 : 0;

        cfg.gridDim = dim3(256, 1, 1);
        cudaLaunchKernelEx(&cfg, k_qkv, lnwp, wqp, wkp, wvp, first, emb, ids,
                           step, plen, pkl, pvl);
        cfg.gridDim = dim3(256, 1, 1);
        cudaLaunchKernelEx(&cfg, k_attn, pk, pv, step, plen, l, ok, ov, wop);
        cfg.gridDim = dim3(128, 1, 1);
        cudaLaunchKernelEx(&cfg, k_wo, wop, wgp, wup);
        cfg.gridDim = dim3(512, 1, 1);
        cudaLaunchKernelEx(&cfg, k_gateup, ln2p, wgp, wup, wdp);
        cfg.gridDim = dim3(256, 1, 1);
        cudaLaunchKernelEx(&cfg, k_wd, wdp, wqn, wkn, wvn);
    }

    // join the copy branch before the tail
    cudaStreamWaitEvent(0, eJ, 0);

    k_lm<<<dim3(32, NPL), 256>>>(lnf, Wlm);
    k_amax1<<<125, 256>>>();
    k_amax2<<<1, 128>>>(out);

    cudaEventDestroy(eF);
    cudaEventDestroy(eJ);
    cudaStreamDestroy(s2);
}